// round 1
// baseline (speedup 1.0000x reference)
#include <cuda_runtime.h>
#include <cuda_bf16.h>
#include <math.h>
#include <float.h>

#define Lc 128
#define Bc 128
#define Ec 300
#define Pc 50
#define FNc 256
#define H2c 100
#define LABc 19
#define FDc 1000

// ---------------- scratch (device globals; allocation-free) ----------------
// X: (B*L, 1000) embed matrix, padded by 8000 floats so conv windows that
// hang off the end of the last batch row never fault (they are masked out).
__device__ float g_X[(size_t)Bc * Lc * FDc + 8000];
// per-(filter,b,f) running max, stored as order-preserving uint keys
__device__ unsigned g_M[3 * Bc * FNc];
// lexical features: (B, 1900); columns 0..1799 = [l1,l2,l3,l4]
__device__ float g_feat[Bc * 1900];

// order-preserving float<->uint key for atomicMax
__device__ __forceinline__ unsigned fkey(float v) {
    unsigned b = __float_as_uint(v);
    return (b & 0x80000000u) ? ~b : (b | 0x80000000u);
}
__device__ __forceinline__ float funkey(unsigned k) {
    return __uint_as_float((k & 0x80000000u) ? (k & 0x7FFFFFFFu) : ~k);
}

// ---------------- init: zero the max keys ----------------
__global__ void init_kernel() {
    int i = blockIdx.x * blockDim.x + threadIdx.x;
    if (i < 3 * Bc * FNc) g_M[i] = 0u;  // smaller than key of any real float
}

// ---------------- build embed matrix X ----------------
// X[b*L+t][0:900]   = [we_pad[t], we_pad[t+1], we_pad[t+2]]  (zeroed for t==0)
// X[b*L+t][900:950] = pos1[p1[b,t]],  [950:1000] = pos2[p2[b,t]]
__global__ void build_embed(const int* __restrict__ inputs,
                            const int* __restrict__ p1, const int* __restrict__ p2,
                            const float* __restrict__ emb,
                            const float* __restrict__ pos1, const float* __restrict__ pos2) {
    int m = blockIdx.x;
    int b = m / Lc, t = m % Lc;
    float* row = g_X + (size_t)m * FDc;

    // padded token row r: r==0 or r==L+1 -> token 0 (pad), else inputs[b][r-1]
    int r0 = t, r1 = t + 1, r2 = t + 2;
    int tok0 = (r0 == 0) ? 0 : inputs[b * Lc + r0 - 1];
    int tok1 = inputs[b * Lc + r1 - 1];                       // 1 <= r1 <= L
    int tok2 = (r2 == Lc + 1) ? 0 : inputs[b * Lc + r2 - 1];
    int i1 = p1[b * Lc + t], i2 = p2[b * Lc + t];

    for (int d = threadIdx.x; d < FDc; d += blockDim.x) {
        float v;
        if (d < 900) {
            if (t == 0) v = 0.0f;
            else if (d < 300) v = emb[(size_t)tok0 * Ec + d];
            else if (d < 600) v = emb[(size_t)tok1 * Ec + (d - 300)];
            else              v = emb[(size_t)tok2 * Ec + (d - 600)];
        } else if (d < 950) {
            v = pos1[(size_t)i1 * Pc + (d - 900)];
        } else {
            v = pos2[(size_t)i2 * Pc + (d - 950)];
        }
        row[d] = v;
    }
}

// ---------------- lexical features l1..l4 ----------------
__global__ void lex_kernel(const int* __restrict__ inputs,
                           const int* __restrict__ e1s, const int* __restrict__ e1e,
                           const int* __restrict__ e2s, const int* __restrict__ e2e,
                           const float* __restrict__ emb) {
    int b = blockIdx.x;
    int d = threadIdx.x;
    if (d >= Ec) return;
    const int* row = inputs + b * Lc;
    int s1 = e1s[b], t1 = e1e[b], s2 = e2s[b], t2 = e2e[b];
    float* fb = g_feat + b * 1900;

    float a = 0.f;
    for (int i = s1; i <= t1; i++) a += emb[(size_t)row[i] * Ec + d];
    fb[d] = a / (float)(t1 - s1 + 1);

    float c = 0.f;
    for (int i = s2; i <= t2; i++) c += emb[(size_t)row[i] * Ec + d];
    fb[300 + d] = c / (float)(t2 - s2 + 1);

    fb[600 + d]  = emb[(size_t)row[s1 - 1] * Ec + d];
    fb[900 + d]  = emb[(size_t)row[t1 + 1] * Ec + d];
    fb[1200 + d] = emb[(size_t)row[s2 - 1] * Ec + d];
    fb[1500 + d] = emb[(size_t)row[t2 + 1] * Ec + d];
}

// ---------------- conv as GEMM + max epilogue ----------------
// z[b,f,t] = dot(X[b*L+t .. +k rows] (contiguous k*1000 floats), W[f])
// grid: (ttile=2, fblock=2, b=128); block 256; tile 64(t) x 128(f), BK=8
template <int KTOT>
__global__ __launch_bounds__(256) void conv_gemm(const float* __restrict__ W,
                                                 int filt, int T) {
    __shared__ float As[2][8][64];
    __shared__ float Bs[2][8][128];
    __shared__ float red[16][128];

    int tid = threadIdx.x;
    int b = blockIdx.z;
    int t0 = blockIdx.x * 64;
    int f0 = blockIdx.y * 128;
    const float* Xb = g_X + (size_t)b * Lc * FDc;

    int tr = tid >> 4, tc = tid & 15;       // compute mapping: 16x16 threads
    int aRow = tid >> 2, aCol = (tid & 3) * 2;   // A load: 64 rows x 8k (float2)
    int bRow = tid >> 1, bCol = (tid & 1) * 4;   // B load: 128 rows x 8k (float4)

    float acc[4][8];
#pragma unroll
    for (int i = 0; i < 4; i++)
#pragma unroll
        for (int j = 0; j < 8; j++) acc[i][j] = 0.f;

    // prologue: stage 0
    {
        float2 av = *(const float2*)(Xb + (size_t)(t0 + aRow) * FDc + aCol);
        float4 bv = *(const float4*)(W + (size_t)(f0 + bRow) * KTOT + bCol);
        As[0][aCol][aRow] = av.x; As[0][aCol + 1][aRow] = av.y;
        Bs[0][bCol][bRow] = bv.x; Bs[0][bCol + 1][bRow] = bv.y;
        Bs[0][bCol + 2][bRow] = bv.z; Bs[0][bCol + 3][bRow] = bv.w;
    }
    __syncthreads();

    const int nk = KTOT / 8;
    for (int kb = 0; kb < nk; kb++) {
        int buf = kb & 1;
        float2 av; float4 bv;
        bool more = (kb + 1 < nk);
        if (more) {
            int k0 = (kb + 1) * 8;
            av = *(const float2*)(Xb + (size_t)(t0 + aRow) * FDc + k0 + aCol);
            bv = *(const float4*)(W + (size_t)(f0 + bRow) * KTOT + k0 + bCol);
        }
#pragma unroll
        for (int k = 0; k < 8; k++) {
            float4 a4 = *(const float4*)&As[buf][k][tr * 4];
            float4 b40 = *(const float4*)&Bs[buf][k][tc * 8];
            float4 b41 = *(const float4*)&Bs[buf][k][tc * 8 + 4];
            float aa[4] = {a4.x, a4.y, a4.z, a4.w};
            float bb[8] = {b40.x, b40.y, b40.z, b40.w, b41.x, b41.y, b41.z, b41.w};
#pragma unroll
            for (int i = 0; i < 4; i++)
#pragma unroll
                for (int j = 0; j < 8; j++) acc[i][j] += aa[i] * bb[j];
        }
        if (more) {
            int nb = buf ^ 1;
            As[nb][aCol][aRow] = av.x; As[nb][aCol + 1][aRow] = av.y;
            Bs[nb][bCol][bRow] = bv.x; Bs[nb][bCol + 1][bRow] = bv.y;
            Bs[nb][bCol + 2][bRow] = bv.z; Bs[nb][bCol + 3][bRow] = bv.w;
        }
        __syncthreads();
    }

    // epilogue: max over valid t rows, then block-reduce over tr, then atomicMax
    float mx[8];
#pragma unroll
    for (int j = 0; j < 8; j++) mx[j] = -FLT_MAX;
#pragma unroll
    for (int i = 0; i < 4; i++) {
        int t = t0 + tr * 4 + i;
        if (t < T) {
#pragma unroll
            for (int j = 0; j < 8; j++) mx[j] = fmaxf(mx[j], acc[i][j]);
        }
    }
#pragma unroll
    for (int j = 0; j < 8; j++) red[tr][tc * 8 + j] = mx[j];
    __syncthreads();
    for (int s = 8; s >= 1; s >>= 1) {
        if (tr < s) {
#pragma unroll
            for (int j = 0; j < 8; j++) {
                int c = tc * 8 + j;
                red[tr][c] = fmaxf(red[tr][c], red[tr + s][c]);
            }
        }
        __syncthreads();
    }
    if (tid < 128) {
        unsigned key = fkey(red[0][tid]);
        atomicMax(&g_M[filt * (Bc * FNc) + b * FNc + f0 + tid], key);
    }
}

// ---------------- head: tanh(max+bias) -> g -> y ----------------
__global__ void mlp_head(const float* __restrict__ cb3, const float* __restrict__ cb4,
                         const float* __restrict__ cb5,
                         const float* __restrict__ W1, const float* __restrict__ b1,
                         const float* __restrict__ W2, const float* __restrict__ b2,
                         float* __restrict__ out) {
    __shared__ float sf[768];
    __shared__ float gbuf[H2c];
    __shared__ float wsum[4][LABc];
    int b = blockIdx.x, tid = threadIdx.x;  // 128 threads

    for (int i = tid; i < 768; i += 128) {
        int kf = i / FNc, f = i % FNc;
        float v = funkey(g_M[kf * (Bc * FNc) + b * FNc + f]);
        const float* cb = (kf == 0) ? cb3 : ((kf == 1) ? cb4 : cb5);
        sf[i] = tanhf(v + cb[f]);
    }
    __syncthreads();

    if (tid < H2c) {
        float s = b1[tid];
        const float* w = W1 + tid * 768;
        for (int c = 0; c < 768; c++) s += w[c] * sf[c];
        gbuf[tid] = tanhf(s);
    }
    __syncthreads();

    float part[LABc];
#pragma unroll
    for (int l = 0; l < LABc; l++) part[l] = 0.f;
    const float* fb = g_feat + b * 1900;
    for (int c = tid; c < 1900; c += 128) {
        float v = (c < 1800) ? fb[c] : gbuf[c - 1800];
#pragma unroll
        for (int l = 0; l < LABc; l++) part[l] += v * W2[l * 1900 + c];
    }
    int lane = tid & 31, wid = tid >> 5;
#pragma unroll
    for (int l = 0; l < LABc; l++) {
        float v = part[l];
        for (int s = 16; s; s >>= 1) v += __shfl_down_sync(0xffffffffu, v, s);
        if (lane == 0) wsum[wid][l] = v;
    }
    __syncthreads();
    if (tid < LABc)
        out[b * LABc + tid] = wsum[0][tid] + wsum[1][tid] + wsum[2][tid] + wsum[3][tid] + b2[tid];
}

// ---------------- launch ----------------
extern "C" void kernel_launch(void* const* d_in, const int* in_sizes, int n_in,
                              void* d_out, int out_size) {
    const int* inputs = (const int*)d_in[0];
    const int* e1s = (const int*)d_in[1];
    const int* e1e = (const int*)d_in[2];
    const int* e2s = (const int*)d_in[3];
    const int* e2e = (const int*)d_in[4];
    const int* p1 = (const int*)d_in[5];
    const int* p2 = (const int*)d_in[6];
    const float* emb = (const float*)d_in[7];
    const float* pos1 = (const float*)d_in[8];
    const float* pos2 = (const float*)d_in[9];
    const float* w3 = (const float*)d_in[10];
    const float* cb3 = (const float*)d_in[11];
    const float* w4 = (const float*)d_in[12];
    const float* cb4 = (const float*)d_in[13];
    const float* w5 = (const float*)d_in[14];
    const float* cb5 = (const float*)d_in[15];
    const float* W1 = (const float*)d_in[16];
    const float* b1 = (const float*)d_in[17];
    const float* W2 = (const float*)d_in[18];
    const float* b2 = (const float*)d_in[19];
    float* out = (float*)d_out;

    init_kernel<<<(3 * Bc * FNc + 255) / 256, 256>>>();
    build_embed<<<Bc * Lc, 256>>>(inputs, p1, p2, emb, pos1, pos2);
    lex_kernel<<<Bc, 320>>>(inputs, e1s, e1e, e2s, e2e, emb);

    dim3 gg(2, 2, Bc);
    conv_gemm<3000><<<gg, 256>>>(w3, 0, Lc - 3 + 1);
    conv_gemm<4000><<<gg, 256>>>(w4, 1, Lc - 4 + 1);
    conv_gemm<5000><<<gg, 256>>>(w5, 2, Lc - 5 + 1);

    mlp_head<<<Bc, 128>>>(cb3, cb4, cb5, W1, b1, W2, b2, out);
}

// round 3
// speedup vs baseline: 3.4363x; 3.4363x over previous
#include <cuda_runtime.h>
#include <cuda_bf16.h>
#include <math.h>
#include <float.h>
#include <stdint.h>

#define Lc 128
#define Bc 128
#define Ec 300
#define Pc 50
#define FNc 256
#define H2c 100
#define LABc 19

// X rows padded to 1024 bf16; 8 extra pad rows so k-window overrun on the last
// batch never faults (zero-init, never written).
#define XW 1024
#define XROWS (Bc * Lc + 8)
// Packed weights: 768 rows x (5 taps x 1024) bf16; cols 1000-1023 zero per tap.
#define WK 5120

__device__ __nv_bfloat16 g_Xh[(size_t)XROWS * XW];
__device__ __nv_bfloat16 g_Xl[(size_t)XROWS * XW];
__device__ __nv_bfloat16 g_Wh[(size_t)768 * WK];
__device__ __nv_bfloat16 g_Wl[(size_t)768 * WK];
__device__ float g_sf[Bc * 768];      // per (b, conv, f) max of conv output
__device__ float g_feat[Bc * 1900];   // lexical features

// ---------------- PTX helpers (sm_80-era; legal on sm_100 plain target) ----
__device__ __forceinline__ uint32_t smem_u32(const void* p) {
    uint32_t a;
    asm("{ .reg .u64 t; cvta.to.shared.u64 t, %1; cvt.u32.u64 %0, t; }" : "=r"(a) : "l"(p));
    return a;
}
__device__ __forceinline__ void cp16(uint32_t saddr, const void* g) {
    asm volatile("cp.async.cg.shared.global [%0], [%1], 16;" :: "r"(saddr), "l"(g) : "memory");
}
#define CP_COMMIT() asm volatile("cp.async.commit_group;" ::: "memory")
#define CP_WAIT1()  asm volatile("cp.async.wait_group 1;" ::: "memory")

#define LDSM4(r0, r1, r2, r3, a)                                              \
    asm volatile("ldmatrix.sync.aligned.m8n8.x4.shared.b16 {%0,%1,%2,%3}, [%4];" \
        : "=r"(r0), "=r"(r1), "=r"(r2), "=r"(r3) : "r"(a))

#define MMA16816(d, a, b)                                                     \
    asm volatile("mma.sync.aligned.m16n8k16.row.col.f32.bf16.bf16.f32 "       \
        "{%0,%1,%2,%3}, {%4,%5,%6,%7}, {%8,%9}, {%0,%1,%2,%3};"               \
        : "+f"((d)[0]), "+f"((d)[1]), "+f"((d)[2]), "+f"((d)[3])              \
        : "r"((a)[0]), "r"((a)[1]), "r"((a)[2]), "r"((a)[3]),                 \
          "r"((b)[0]), "r"((b)[1]))

// ---------------- embed build (hi/lo bf16 split) ----------------
__global__ void build_embed(const int* __restrict__ inputs,
                            const int* __restrict__ p1, const int* __restrict__ p2,
                            const float* __restrict__ emb,
                            const float* __restrict__ pos1, const float* __restrict__ pos2) {
    int m = blockIdx.x;
    int b = m / Lc, t = m % Lc;
    __nv_bfloat16* rh = g_Xh + (size_t)m * XW;
    __nv_bfloat16* rl = g_Xl + (size_t)m * XW;

    int tok0 = (t == 0) ? 0 : inputs[b * Lc + t - 1];
    int tok1 = inputs[b * Lc + t];
    int tok2 = (t + 2 == Lc + 1) ? 0 : inputs[b * Lc + t + 1];
    int i1 = p1[b * Lc + t], i2 = p2[b * Lc + t];

    for (int d = threadIdx.x; d < 1000; d += blockDim.x) {
        float v;
        if (d < 900) {
            if (t == 0) v = 0.0f;
            else if (d < 300) v = emb[(size_t)tok0 * Ec + d];
            else if (d < 600) v = emb[(size_t)tok1 * Ec + (d - 300)];
            else              v = emb[(size_t)tok2 * Ec + (d - 600)];
        } else if (d < 950) {
            v = pos1[(size_t)i1 * Pc + (d - 900)];
        } else {
            v = pos2[(size_t)i2 * Pc + (d - 950)];
        }
        __nv_bfloat16 hi = __float2bfloat16_rn(v);
        rh[d] = hi;
        rl[d] = __float2bfloat16_rn(v - __bfloat162float(hi));
    }
}

// ---------------- weight pack (hi/lo bf16 split, taps padded to 1024) ------
__global__ void pack_w(const float* __restrict__ w3, const float* __restrict__ w4,
                       const float* __restrict__ w5) {
    int fp = blockIdx.x;              // 0..767
    int conv = fp >> 8, f = fp & 255;
    int k = 3 + conv;
    const float* w = (conv == 0) ? w3 : ((conv == 1) ? w4 : w5);
    for (int idx = threadIdx.x; idx < WK; idx += blockDim.x) {
        int tap = idx >> 10, d = idx & 1023;
        float v = (tap < k && d < 1000) ? w[((size_t)f * k + tap) * 1000 + d] : 0.0f;
        __nv_bfloat16 hi = __float2bfloat16_rn(v);
        g_Wh[(size_t)fp * WK + idx] = hi;
        g_Wl[(size_t)fp * WK + idx] = __float2bfloat16_rn(v - __bfloat162float(hi));
    }
}

// ---------------- lexical features ----------------
__global__ void lex_kernel(const int* __restrict__ inputs,
                           const int* __restrict__ e1s, const int* __restrict__ e1e,
                           const int* __restrict__ e2s, const int* __restrict__ e2e,
                           const float* __restrict__ emb) {
    int b = blockIdx.x;
    int d = threadIdx.x;
    if (d >= Ec) return;
    const int* row = inputs + b * Lc;
    int s1 = e1s[b], t1 = e1e[b], s2 = e2s[b], t2 = e2e[b];
    float* fb = g_feat + b * 1900;

    float a = 0.f;
    for (int i = s1; i <= t1; i++) a += emb[(size_t)row[i] * Ec + d];
    fb[d] = a / (float)(t1 - s1 + 1);
    float c = 0.f;
    for (int i = s2; i <= t2; i++) c += emb[(size_t)row[i] * Ec + d];
    fb[300 + d] = c / (float)(t2 - s2 + 1);
    fb[600 + d]  = emb[(size_t)row[s1 - 1] * Ec + d];
    fb[900 + d]  = emb[(size_t)row[t1 + 1] * Ec + d];
    fb[1200 + d] = emb[(size_t)row[s2 - 1] * Ec + d];
    fb[1500 + d] = emb[(size_t)row[t2 + 1] * Ec + d];
}

// ---------------- fused conv GEMM (mma.sync bf16, 3-term split) ------------
// CTA = (b, conv, nhalf): D[t=0..127, f=f0..f0+127] over K = (3+conv)*1024.
// A[t][k] = g_X[(b*L + t)*1024 + k]  (windows contiguous by construction).
// Epilogue: masked max over t -> g_sf (no atomics; CTA owns full t range).
#define BK 32
#define ROWB 80            /* 64B data + 16B pad per smem row: conflict-free */
#define OFF_AL 10240
#define OFF_BH 20480
#define OFF_BL 30720
#define STAGE  40960
#define NSTAGE 3
#define GEMM_SMEM (NSTAGE * STAGE)

__device__ __forceinline__ void load_stage(uint32_t sb, int buf, int kb, int tid,
                                           size_t brow, int w0) {
    uint32_t s0 = sb + (uint32_t)buf * STAGE;
#pragma unroll
    for (int i = 0; i < 2; i++) {
        int ch = tid * 2 + i;
        int row = ch >> 2, c = ch & 3;
        uint32_t so = (uint32_t)(row * ROWB + c * 16);
        size_t ka = (brow + row) * (size_t)XW + kb * BK + c * 8;
        size_t kw = (size_t)(w0 + row) * WK + kb * BK + c * 8;
        cp16(s0 + so,           g_Xh + ka);
        cp16(s0 + OFF_AL + so,  g_Xl + ka);
        cp16(s0 + OFF_BH + so,  g_Wh + kw);
        cp16(s0 + OFF_BL + so,  g_Wl + kw);
    }
}

__global__ void __launch_bounds__(256, 1) gemm_kernel() {
    extern __shared__ char smem[];
    __shared__ float red[4][128];
    uint32_t sb = smem_u32(smem);
    int tid = threadIdx.x, lane = tid & 31, warp = tid >> 5;
    int wm = warp & 3, wn = warp >> 2;        // 4 m-warps x 2 n-warps
    int b = blockIdx.x, conv = blockIdx.y, nb = blockIdx.z;
    int f0 = nb * 128;
    size_t brow = (size_t)b * Lc;
    int w0 = conv * 256 + f0;
    int niter = 96 + 32 * conv;               // K/BK = 3072/4096/5120 over 32

    float d[2][8][4];
#pragma unroll
    for (int mt = 0; mt < 2; mt++)
#pragma unroll
        for (int nt = 0; nt < 8; nt++)
#pragma unroll
            for (int j = 0; j < 4; j++) d[mt][nt][j] = 0.f;

    // ldmatrix per-lane base offsets (relative to stage base)
    uint32_t aRel = (uint32_t)((wm * 32 + (lane & 7) + ((lane & 8) ? 8 : 0)) * ROWB
                               + ((lane & 16) ? 16 : 0));
    uint32_t bRel = (uint32_t)(OFF_BH
                               + (wn * 64 + (lane & 7) + ((lane & 16) ? 8 : 0)) * ROWB
                               + ((lane & 8) ? 16 : 0));

    load_stage(sb, 0, 0, tid, brow, w0);
    CP_COMMIT();
    load_stage(sb, 1, 1, tid, brow, w0);
    CP_COMMIT();

    for (int it = 0; it < niter; it++) {
        CP_WAIT1();
        __syncthreads();
        int pf = it + 2;
        if (pf < niter) load_stage(sb, pf % NSTAGE, pf, tid, brow, w0);
        CP_COMMIT();

        uint32_t base = sb + (uint32_t)(it % NSTAGE) * STAGE;
#pragma unroll
        for (int kc = 0; kc < 2; kc++) {
            uint32_t aH[2][4], aL[2][4], bH[8][2], bL[8][2];
#pragma unroll
            for (int mt = 0; mt < 2; mt++) {
                uint32_t ad = base + aRel + mt * (16 * ROWB) + kc * 32;
                LDSM4(aH[mt][0], aH[mt][1], aH[mt][2], aH[mt][3], ad);
                LDSM4(aL[mt][0], aL[mt][1], aL[mt][2], aL[mt][3], ad + OFF_AL);
            }
#pragma unroll
            for (int np = 0; np < 4; np++) {
                uint32_t bd = base + bRel + np * (16 * ROWB) + kc * 32;
                uint32_t r0, r1, r2, r3;
                LDSM4(r0, r1, r2, r3, bd);
                bH[2 * np][0] = r0; bH[2 * np][1] = r1;
                bH[2 * np + 1][0] = r2; bH[2 * np + 1][1] = r3;
                LDSM4(r0, r1, r2, r3, bd + OFF_AL);
                bL[2 * np][0] = r0; bL[2 * np][1] = r1;
                bL[2 * np + 1][0] = r2; bL[2 * np + 1][1] = r3;
            }
#pragma unroll
            for (int mt = 0; mt < 2; mt++)
#pragma unroll
                for (int nt = 0; nt < 8; nt++) {
                    MMA16816(d[mt][nt], aH[mt], bH[nt]);
                    MMA16816(d[mt][nt], aH[mt], bL[nt]);
                    MMA16816(d[mt][nt], aL[mt], bH[nt]);
                }
        }
    }

    // ---- epilogue: masked max over t ----
    int T = 126 - conv;                       // valid t count = L - k + 1
    int g = lane >> 2;
#pragma unroll
    for (int nt = 0; nt < 8; nt++) {
        float m0 = -FLT_MAX, m1 = -FLT_MAX;
#pragma unroll
        for (int mt = 0; mt < 2; mt++) {
            int r0 = wm * 32 + mt * 16 + g;
            if (r0 < T)     { m0 = fmaxf(m0, d[mt][nt][0]); m1 = fmaxf(m1, d[mt][nt][1]); }
            if (r0 + 8 < T) { m0 = fmaxf(m0, d[mt][nt][2]); m1 = fmaxf(m1, d[mt][nt][3]); }
        }
#pragma unroll
        for (int off = 4; off < 32; off <<= 1) {
            m0 = fmaxf(m0, __shfl_xor_sync(0xffffffffu, m0, off));
            m1 = fmaxf(m1, __shfl_xor_sync(0xffffffffu, m1, off));
        }
        if (g == 0) {
            int nc = wn * 64 + nt * 8 + (lane & 3) * 2;
            red[wm][nc] = m0;
            red[wm][nc + 1] = m1;
        }
    }
    __syncthreads();
    if (tid < 128) {
        float v = fmaxf(fmaxf(red[0][tid], red[1][tid]),
                        fmaxf(red[2][tid], red[3][tid]));
        g_sf[b * 768 + conv * 256 + f0 + tid] = v;
    }
}

// ---------------- head ----------------
__global__ void mlp_head(const float* __restrict__ cb3, const float* __restrict__ cb4,
                         const float* __restrict__ cb5,
                         const float* __restrict__ W1, const float* __restrict__ b1,
                         const float* __restrict__ W2, const float* __restrict__ b2,
                         float* __restrict__ out) {
    __shared__ float sf[768];
    __shared__ float gbuf[H2c];
    __shared__ float wsum[4][LABc];
    int b = blockIdx.x, tid = threadIdx.x;  // 128 threads

    for (int i = tid; i < 768; i += 128) {
        int kf = i >> 8, f = i & 255;
        const float* cb = (kf == 0) ? cb3 : ((kf == 1) ? cb4 : cb5);
        sf[i] = tanhf(g_sf[b * 768 + i] + cb[f]);
    }
    __syncthreads();

    if (tid < H2c) {
        float s = b1[tid];
        const float* w = W1 + tid * 768;
        for (int c = 0; c < 768; c++) s += w[c] * sf[c];
        gbuf[tid] = tanhf(s);
    }
    __syncthreads();

    float part[LABc];
#pragma unroll
    for (int l = 0; l < LABc; l++) part[l] = 0.f;
    const float* fb = g_feat + b * 1900;
    for (int c = tid; c < 1900; c += 128) {
        float v = (c < 1800) ? fb[c] : gbuf[c - 1800];
#pragma unroll
        for (int l = 0; l < LABc; l++) part[l] += v * W2[l * 1900 + c];
    }
    int lane = tid & 31, wid = tid >> 5;
#pragma unroll
    for (int l = 0; l < LABc; l++) {
        float v = part[l];
        for (int s = 16; s; s >>= 1) v += __shfl_down_sync(0xffffffffu, v, s);
        if (lane == 0) wsum[wid][l] = v;
    }
    __syncthreads();
    if (tid < LABc)
        out[b * LABc + tid] = wsum[0][tid] + wsum[1][tid] + wsum[2][tid] + wsum[3][tid] + b2[tid];
}

// ---------------- launch ----------------
extern "C" void kernel_launch(void* const* d_in, const int* in_sizes, int n_in,
                              void* d_out, int out_size) {
    const int* inputs = (const int*)d_in[0];
    const int* e1s = (const int*)d_in[1];
    const int* e1e = (const int*)d_in[2];
    const int* e2s = (const int*)d_in[3];
    const int* e2e = (const int*)d_in[4];
    const int* p1 = (const int*)d_in[5];
    const int* p2 = (const int*)d_in[6];
    const float* emb = (const float*)d_in[7];
    const float* pos1 = (const float*)d_in[8];
    const float* pos2 = (const float*)d_in[9];
    const float* w3 = (const float*)d_in[10];
    const float* cb3 = (const float*)d_in[11];
    const float* w4 = (const float*)d_in[12];
    const float* cb4 = (const float*)d_in[13];
    const float* w5 = (const float*)d_in[14];
    const float* cb5 = (const float*)d_in[15];
    const float* W1 = (const float*)d_in[16];
    const float* b1 = (const float*)d_in[17];
    const float* W2 = (const float*)d_in[18];
    const float* b2 = (const float*)d_in[19];
    float* out = (float*)d_out;

    static int cfg_done = 0;
    if (!cfg_done) {
        cudaFuncSetAttribute(gemm_kernel, cudaFuncAttributeMaxDynamicSharedMemorySize,
                             GEMM_SMEM);
        cfg_done = 1;
    }

    build_embed<<<Bc * Lc, 256>>>(inputs, p1, p2, emb, pos1, pos2);
    pack_w<<<768, 256>>>(w3, w4, w5);
    lex_kernel<<<Bc, 320>>>(inputs, e1s, e1e, e2s, e2e, emb);

    dim3 gg(Bc, 3, 2);
    gemm_kernel<<<gg, 256, GEMM_SMEM>>>();

    mlp_head<<<Bc, 128>>>(cb3, cb4, cb5, W1, b1, W2, b2, out);
}

// round 4
// speedup vs baseline: 8.4863x; 2.4696x over previous
#include <cuda_runtime.h>
#include <cuda_fp16.h>
#include <math.h>
#include <float.h>
#include <stdint.h>

#define Lc 128
#define Bc 128
#define Ec 300
#define Pc 50
#define FNc 256
#define H2c 100
#define LABc 19

// X rows padded to 1024 fp16; 8 extra pad rows so k-window overrun on the last
// batch never faults (zero-init, never written).
#define XW 1024
#define XROWS (Bc * Lc + 8)
// Packed weights: 768 rows x (5 taps x 1024) fp16; cols 1000-1023 zero per tap.
#define WK 5120

__device__ __half g_X[(size_t)XROWS * XW];
__device__ __half g_W[(size_t)768 * WK];
__device__ float g_sf[Bc * 768];      // per (b, conv, f) max of conv output
__device__ float g_feat[Bc * 1900];   // lexical features

// ---------------- PTX helpers ----------------
__device__ __forceinline__ uint32_t smem_u32(const void* p) {
    uint32_t a;
    asm("{ .reg .u64 t; cvta.to.shared.u64 t, %1; cvt.u32.u64 %0, t; }" : "=r"(a) : "l"(p));
    return a;
}
__device__ __forceinline__ void cp16(uint32_t saddr, const void* g) {
    asm volatile("cp.async.cg.shared.global [%0], [%1], 16;" :: "r"(saddr), "l"(g) : "memory");
}
#define CP_COMMIT() asm volatile("cp.async.commit_group;" ::: "memory")
#define CP_WAIT1()  asm volatile("cp.async.wait_group 1;" ::: "memory")

#define LDSM4(r0, r1, r2, r3, a)                                              \
    asm volatile("ldmatrix.sync.aligned.m8n8.x4.shared.b16 {%0,%1,%2,%3}, [%4];" \
        : "=r"(r0), "=r"(r1), "=r"(r2), "=r"(r3) : "r"(a))

#define MMA16816(d, a, b)                                                     \
    asm volatile("mma.sync.aligned.m16n8k16.row.col.f32.f16.f16.f32 "         \
        "{%0,%1,%2,%3}, {%4,%5,%6,%7}, {%8,%9}, {%0,%1,%2,%3};"               \
        : "+f"((d)[0]), "+f"((d)[1]), "+f"((d)[2]), "+f"((d)[3])              \
        : "r"((a)[0]), "r"((a)[1]), "r"((a)[2]), "r"((a)[3]),                 \
          "r"((b)[0]), "r"((b)[1]))

// ---------------- embed build (fp16) ----------------
__global__ void build_embed(const int* __restrict__ inputs,
                            const int* __restrict__ p1, const int* __restrict__ p2,
                            const float* __restrict__ emb,
                            const float* __restrict__ pos1, const float* __restrict__ pos2) {
    int m = blockIdx.x;
    int b = m / Lc, t = m % Lc;
    __half* row = g_X + (size_t)m * XW;

    int tok0 = (t == 0) ? 0 : inputs[b * Lc + t - 1];
    int tok1 = inputs[b * Lc + t];
    int tok2 = (t + 2 == Lc + 1) ? 0 : inputs[b * Lc + t + 1];
    int i1 = p1[b * Lc + t], i2 = p2[b * Lc + t];

    for (int d = threadIdx.x; d < 1000; d += blockDim.x) {
        float v;
        if (d < 900) {
            if (t == 0) v = 0.0f;
            else if (d < 300) v = emb[(size_t)tok0 * Ec + d];
            else if (d < 600) v = emb[(size_t)tok1 * Ec + (d - 300)];
            else              v = emb[(size_t)tok2 * Ec + (d - 600)];
        } else if (d < 950) {
            v = pos1[(size_t)i1 * Pc + (d - 900)];
        } else {
            v = pos2[(size_t)i2 * Pc + (d - 950)];
        }
        row[d] = __float2half_rn(v);
    }
}

// ---------------- weight pack (fp16, taps padded to 1024) ------------------
__global__ void pack_w(const float* __restrict__ w3, const float* __restrict__ w4,
                       const float* __restrict__ w5) {
    int fp = blockIdx.x;              // 0..767
    int conv = fp >> 8, f = fp & 255;
    int k = 3 + conv;
    const float* w = (conv == 0) ? w3 : ((conv == 1) ? w4 : w5);
    for (int idx = threadIdx.x; idx < WK; idx += blockDim.x) {
        int tap = idx >> 10, d = idx & 1023;
        float v = (tap < k && d < 1000) ? w[((size_t)f * k + tap) * 1000 + d] : 0.0f;
        g_W[(size_t)fp * WK + idx] = __float2half_rn(v);
    }
}

// ---------------- lexical features ----------------
__global__ void lex_kernel(const int* __restrict__ inputs,
                           const int* __restrict__ e1s, const int* __restrict__ e1e,
                           const int* __restrict__ e2s, const int* __restrict__ e2e,
                           const float* __restrict__ emb) {
    int b = blockIdx.x;
    int d = threadIdx.x;
    if (d >= Ec) return;
    const int* row = inputs + b * Lc;
    int s1 = e1s[b], t1 = e1e[b], s2 = e2s[b], t2 = e2e[b];
    float* fb = g_feat + b * 1900;

    float a = 0.f;
    for (int i = s1; i <= t1; i++) a += emb[(size_t)row[i] * Ec + d];
    fb[d] = a / (float)(t1 - s1 + 1);
    float c = 0.f;
    for (int i = s2; i <= t2; i++) c += emb[(size_t)row[i] * Ec + d];
    fb[300 + d] = c / (float)(t2 - s2 + 1);
    fb[600 + d]  = emb[(size_t)row[s1 - 1] * Ec + d];
    fb[900 + d]  = emb[(size_t)row[t1 + 1] * Ec + d];
    fb[1200 + d] = emb[(size_t)row[s2 - 1] * Ec + d];
    fb[1500 + d] = emb[(size_t)row[t2 + 1] * Ec + d];
}

// ---------------- fused conv GEMM (single-pass fp16 mma.sync) --------------
// CTA = (b, conv, nhalf): D[t=0..127, f=f0..f0+127] over K = (3+conv)*1024.
// Epilogue: masked max over t -> g_sf (no atomics; CTA owns full t range).
#define BK 32
#define ROWB 80            /* 64B data + 16B pad per smem row: conflict-free */
#define OFF_B 10240
#define STAGE 20480
#define NSTAGE 3
#define GEMM_SMEM (NSTAGE * STAGE)

__device__ __forceinline__ void load_stage(uint32_t sb, int buf, int kb, int tid,
                                           size_t brow, int w0) {
    uint32_t s0 = sb + (uint32_t)buf * STAGE;
#pragma unroll
    for (int i = 0; i < 2; i++) {
        int ch = tid * 2 + i;
        int row = ch >> 2, c = ch & 3;
        uint32_t so = (uint32_t)(row * ROWB + c * 16);
        cp16(s0 + so,         g_X + (brow + row) * (size_t)XW + kb * BK + c * 8);
        cp16(s0 + OFF_B + so, g_W + (size_t)(w0 + row) * WK + kb * BK + c * 8);
    }
}

__global__ void __launch_bounds__(256, 2) gemm_kernel() {
    extern __shared__ char smem[];
    __shared__ float red[4][128];
    uint32_t sb = smem_u32(smem);
    int tid = threadIdx.x, lane = tid & 31, warp = tid >> 5;
    int wm = warp & 3, wn = warp >> 2;        // 4 m-warps x 2 n-warps
    int b = blockIdx.x, conv = blockIdx.y, nb = blockIdx.z;
    int f0 = nb * 128;
    size_t brow = (size_t)b * Lc;
    int w0 = conv * 256 + f0;
    int niter = 96 + 32 * conv;               // K/BK = 3072/4096/5120 over 32

    float d[2][8][4];
#pragma unroll
    for (int mt = 0; mt < 2; mt++)
#pragma unroll
        for (int nt = 0; nt < 8; nt++)
#pragma unroll
            for (int j = 0; j < 4; j++) d[mt][nt][j] = 0.f;

    uint32_t aRel = (uint32_t)((wm * 32 + (lane & 7) + ((lane & 8) ? 8 : 0)) * ROWB
                               + ((lane & 16) ? 16 : 0));
    uint32_t bRel = (uint32_t)(OFF_B
                               + (wn * 64 + (lane & 7) + ((lane & 16) ? 8 : 0)) * ROWB
                               + ((lane & 8) ? 16 : 0));

    load_stage(sb, 0, 0, tid, brow, w0);
    CP_COMMIT();
    load_stage(sb, 1, 1, tid, brow, w0);
    CP_COMMIT();

    for (int it = 0; it < niter; it++) {
        CP_WAIT1();
        __syncthreads();
        int pf = it + 2;
        if (pf < niter) load_stage(sb, pf % NSTAGE, pf, tid, brow, w0);
        CP_COMMIT();

        uint32_t base = sb + (uint32_t)(it % NSTAGE) * STAGE;
#pragma unroll
        for (int kc = 0; kc < 2; kc++) {
            uint32_t aH[2][4], bH[8][2];
#pragma unroll
            for (int mt = 0; mt < 2; mt++) {
                uint32_t ad = base + aRel + mt * (16 * ROWB) + kc * 32;
                LDSM4(aH[mt][0], aH[mt][1], aH[mt][2], aH[mt][3], ad);
            }
#pragma unroll
            for (int np = 0; np < 4; np++) {
                uint32_t bd = base + bRel + np * (16 * ROWB) + kc * 32;
                uint32_t r0, r1, r2, r3;
                LDSM4(r0, r1, r2, r3, bd);
                bH[2 * np][0] = r0; bH[2 * np][1] = r1;
                bH[2 * np + 1][0] = r2; bH[2 * np + 1][1] = r3;
            }
#pragma unroll
            for (int mt = 0; mt < 2; mt++)
#pragma unroll
                for (int nt = 0; nt < 8; nt++)
                    MMA16816(d[mt][nt], aH[mt], bH[nt]);
        }
    }

    // ---- epilogue: masked max over t ----
    int T = 126 - conv;                       // valid t count = L - k + 1
    int g = lane >> 2;
#pragma unroll
    for (int nt = 0; nt < 8; nt++) {
        float m0 = -FLT_MAX, m1 = -FLT_MAX;
#pragma unroll
        for (int mt = 0; mt < 2; mt++) {
            int r0 = wm * 32 + mt * 16 + g;
            if (r0 < T)     { m0 = fmaxf(m0, d[mt][nt][0]); m1 = fmaxf(m1, d[mt][nt][1]); }
            if (r0 + 8 < T) { m0 = fmaxf(m0, d[mt][nt][2]); m1 = fmaxf(m1, d[mt][nt][3]); }
        }
#pragma unroll
        for (int off = 4; off < 32; off <<= 1) {
            m0 = fmaxf(m0, __shfl_xor_sync(0xffffffffu, m0, off));
            m1 = fmaxf(m1, __shfl_xor_sync(0xffffffffu, m1, off));
        }
        if (g == 0) {
            int nc = wn * 64 + nt * 8 + (lane & 3) * 2;
            red[wm][nc] = m0;
            red[wm][nc + 1] = m1;
        }
    }
    __syncthreads();
    if (tid < 128) {
        float v = fmaxf(fmaxf(red[0][tid], red[1][tid]),
                        fmaxf(red[2][tid], red[3][tid]));
        g_sf[b * 768 + conv * 256 + f0 + tid] = v;
    }
}

// ---------------- head ----------------
__global__ void mlp_head(const float* __restrict__ cb3, const float* __restrict__ cb4,
                         const float* __restrict__ cb5,
                         const float* __restrict__ W1, const float* __restrict__ b1,
                         const float* __restrict__ W2, const float* __restrict__ b2,
                         float* __restrict__ out) {
    __shared__ float sf[768];
    __shared__ float gbuf[H2c];
    __shared__ float wsum[4][LABc];
    int b = blockIdx.x, tid = threadIdx.x;  // 128 threads

    for (int i = tid; i < 768; i += 128) {
        int kf = i >> 8, f = i & 255;
        const float* cb = (kf == 0) ? cb3 : ((kf == 1) ? cb4 : cb5);
        sf[i] = tanhf(g_sf[b * 768 + i] + cb[f]);
    }
    __syncthreads();

    if (tid < H2c) {
        float s = b1[tid];
        const float* w = W1 + tid * 768;
        for (int c = 0; c < 768; c++) s += w[c] * sf[c];
        gbuf[tid] = tanhf(s);
    }
    __syncthreads();

    float part[LABc];
#pragma unroll
    for (int l = 0; l < LABc; l++) part[l] = 0.f;
    const float* fb = g_feat + b * 1900;
    for (int c = tid; c < 1900; c += 128) {
        float v = (c < 1800) ? fb[c] : gbuf[c - 1800];
#pragma unroll
        for (int l = 0; l < LABc; l++) part[l] += v * W2[l * 1900 + c];
    }
    int lane = tid & 31, wid = tid >> 5;
#pragma unroll
    for (int l = 0; l < LABc; l++) {
        float v = part[l];
        for (int s = 16; s; s >>= 1) v += __shfl_down_sync(0xffffffffu, v, s);
        if (lane == 0) wsum[wid][l] = v;
    }
    __syncthreads();
    if (tid < LABc)
        out[b * LABc + tid] = wsum[0][tid] + wsum[1][tid] + wsum[2][tid] + wsum[3][tid] + b2[tid];
}

// ---------------- launch ----------------
extern "C" void kernel_launch(void* const* d_in, const int* in_sizes, int n_in,
                              void* d_out, int out_size) {
    const int* inputs = (const int*)d_in[0];
    const int* e1s = (const int*)d_in[1];
    const int* e1e = (const int*)d_in[2];
    const int* e2s = (const int*)d_in[3];
    const int* e2e = (const int*)d_in[4];
    const int* p1 = (const int*)d_in[5];
    const int* p2 = (const int*)d_in[6];
    const float* emb = (const float*)d_in[7];
    const float* pos1 = (const float*)d_in[8];
    const float* pos2 = (const float*)d_in[9];
    const float* w3 = (const float*)d_in[10];
    const float* cb3 = (const float*)d_in[11];
    const float* w4 = (const float*)d_in[12];
    const float* cb4 = (const float*)d_in[13];
    const float* w5 = (const float*)d_in[14];
    const float* cb5 = (const float*)d_in[15];
    const float* W1 = (const float*)d_in[16];
    const float* b1 = (const float*)d_in[17];
    const float* W2 = (const float*)d_in[18];
    const float* b2 = (const float*)d_in[19];
    float* out = (float*)d_out;

    static int cfg_done = 0;
    if (!cfg_done) {
        cudaFuncSetAttribute(gemm_kernel, cudaFuncAttributeMaxDynamicSharedMemorySize,
                             GEMM_SMEM);
        cfg_done = 1;
    }

    build_embed<<<Bc * Lc, 256>>>(inputs, p1, p2, emb, pos1, pos2);
    pack_w<<<768, 256>>>(w3, w4, w5);
    lex_kernel<<<Bc, 320>>>(inputs, e1s, e1e, e2s, e2e, emb);

    dim3 gg(Bc, 3, 2);
    gemm_kernel<<<gg, 256, GEMM_SMEM>>>();

    mlp_head<<<Bc, 128>>>(cb3, cb4, cb5, W1, b1, W2, b2, out);
}

// round 5
// speedup vs baseline: 8.9238x; 1.0516x over previous
#include <cuda_runtime.h>
#include <cuda_fp16.h>
#include <math.h>
#include <float.h>
#include <stdint.h>

#define Lc 128
#define Bc 128
#define Ec 300
#define Pc 50
#define FNc 256
#define H2c 100
#define LABc 19

#define XW 1024
#define XROWS (Bc * Lc + 8)
#define WK 5120

__device__ __half g_X[(size_t)XROWS * XW];
__device__ __half g_W[(size_t)768 * WK];
__device__ float g_sf[Bc * 768];
__device__ float g_feat[Bc * 1900];

// ---------------- PTX helpers ----------------
__device__ __forceinline__ uint32_t smem_u32(const void* p) {
    uint32_t a;
    asm("{ .reg .u64 t; cvta.to.shared.u64 t, %1; cvt.u32.u64 %0, t; }" : "=r"(a) : "l"(p));
    return a;
}
__device__ __forceinline__ void cp16(uint32_t saddr, const void* g) {
    asm volatile("cp.async.cg.shared.global [%0], [%1], 16;" :: "r"(saddr), "l"(g) : "memory");
}
#define CP_COMMIT() asm volatile("cp.async.commit_group;" ::: "memory")
#define CP_WAIT2()  asm volatile("cp.async.wait_group 2;" ::: "memory")

#define LDSM4(r0, r1, r2, r3, a)                                              \
    asm volatile("ldmatrix.sync.aligned.m8n8.x4.shared.b16 {%0,%1,%2,%3}, [%4];" \
        : "=r"(r0), "=r"(r1), "=r"(r2), "=r"(r3) : "r"(a))

#define MMA16816(d, a, b)                                                     \
    asm volatile("mma.sync.aligned.m16n8k16.row.col.f32.f16.f16.f32 "         \
        "{%0,%1,%2,%3}, {%4,%5,%6,%7}, {%8,%9}, {%0,%1,%2,%3};"               \
        : "+f"((d)[0]), "+f"((d)[1]), "+f"((d)[2]), "+f"((d)[3])              \
        : "r"((a)[0]), "r"((a)[1]), "r"((a)[2]), "r"((a)[3]),                 \
          "r"((b)[0]), "r"((b)[1]))

// ---------------- fused prep: embed + weight pack + lex --------------------
// blocks [0, B*L)               : build_embed (one (b,t) row each)
// blocks [B*L, B*L+768)         : pack_w (one packed weight row each)
// blocks [B*L+768, B*L+768+B)   : lex features (one batch each)
__global__ void prep_kernel(const int* __restrict__ inputs,
                            const int* __restrict__ p1, const int* __restrict__ p2,
                            const float* __restrict__ emb,
                            const float* __restrict__ pos1, const float* __restrict__ pos2,
                            const float* __restrict__ w3, const float* __restrict__ w4,
                            const float* __restrict__ w5,
                            const int* __restrict__ e1s, const int* __restrict__ e1e,
                            const int* __restrict__ e2s, const int* __restrict__ e2e) {
    int blk = blockIdx.x;
    if (blk < Bc * Lc) {
        int m = blk;
        int b = m / Lc, t = m % Lc;
        __half* row = g_X + (size_t)m * XW;
        int tok0 = (t == 0) ? 0 : inputs[b * Lc + t - 1];
        int tok1 = inputs[b * Lc + t];
        int tok2 = (t + 2 == Lc + 1) ? 0 : inputs[b * Lc + t + 1];
        int i1 = p1[b * Lc + t], i2 = p2[b * Lc + t];
        for (int d = threadIdx.x; d < 1000; d += blockDim.x) {
            float v;
            if (d < 900) {
                if (t == 0) v = 0.0f;
                else if (d < 300) v = emb[(size_t)tok0 * Ec + d];
                else if (d < 600) v = emb[(size_t)tok1 * Ec + (d - 300)];
                else              v = emb[(size_t)tok2 * Ec + (d - 600)];
            } else if (d < 950) {
                v = pos1[(size_t)i1 * Pc + (d - 900)];
            } else {
                v = pos2[(size_t)i2 * Pc + (d - 950)];
            }
            row[d] = __float2half_rn(v);
        }
    } else if (blk < Bc * Lc + 768) {
        int fp = blk - Bc * Lc;
        int conv = fp >> 8, f = fp & 255;
        int k = 3 + conv;
        const float* w = (conv == 0) ? w3 : ((conv == 1) ? w4 : w5);
        for (int idx = threadIdx.x; idx < WK; idx += blockDim.x) {
            int tap = idx >> 10, d = idx & 1023;
            float v = (tap < k && d < 1000) ? w[((size_t)f * k + tap) * 1000 + d] : 0.0f;
            g_W[(size_t)fp * WK + idx] = __float2half_rn(v);
        }
    } else {
        int b = blk - Bc * Lc - 768;
        const int* row = inputs + b * Lc;
        int s1 = e1s[b], t1 = e1e[b], s2 = e2s[b], t2 = e2e[b];
        float* fb = g_feat + b * 1900;
        for (int d = threadIdx.x; d < Ec; d += blockDim.x) {
            float a = 0.f;
            for (int i = s1; i <= t1; i++) a += emb[(size_t)row[i] * Ec + d];
            fb[d] = a / (float)(t1 - s1 + 1);
            float c = 0.f;
            for (int i = s2; i <= t2; i++) c += emb[(size_t)row[i] * Ec + d];
            fb[300 + d] = c / (float)(t2 - s2 + 1);
            fb[600 + d]  = emb[(size_t)row[s1 - 1] * Ec + d];
            fb[900 + d]  = emb[(size_t)row[t1 + 1] * Ec + d];
            fb[1200 + d] = emb[(size_t)row[s2 - 1] * Ec + d];
            fb[1500 + d] = emb[(size_t)row[t2 + 1] * Ec + d];
        }
    }
}

// ---------------- fused conv GEMM (single-pass fp16 mma.sync) --------------
#define BK 32
#define ROWB 80
#define OFF_B 10240
#define STAGE 20480
#define NSTAGE 4
#define GEMM_SMEM (NSTAGE * STAGE)

__device__ __forceinline__ void load_stage(uint32_t sb, int buf, int kb, int tid,
                                           size_t brow, int w0) {
    uint32_t s0 = sb + (uint32_t)buf * STAGE;
#pragma unroll
    for (int i = 0; i < 2; i++) {
        int ch = tid * 2 + i;
        int row = ch >> 2, c = ch & 3;
        uint32_t so = (uint32_t)(row * ROWB + c * 16);
        cp16(s0 + so,         g_X + (brow + row) * (size_t)XW + kb * BK + c * 8);
        cp16(s0 + OFF_B + so, g_W + (size_t)(w0 + row) * WK + kb * BK + c * 8);
    }
}

__global__ void __launch_bounds__(256, 2) gemm_kernel() {
    extern __shared__ char smem[];
    __shared__ float red[4][128];
    uint32_t sb = smem_u32(smem);
    int tid = threadIdx.x, lane = tid & 31, warp = tid >> 5;
    int wm = warp & 3, wn = warp >> 2;
    int b = blockIdx.x, nb = blockIdx.z;
    int conv = 2 - blockIdx.y;                // longest jobs (conv5) first
    int f0 = nb * 128;
    size_t brow = (size_t)b * Lc;
    int w0 = conv * 256 + f0;
    int niter = 96 + 32 * conv;

    float d[2][8][4];
#pragma unroll
    for (int mt = 0; mt < 2; mt++)
#pragma unroll
        for (int nt = 0; nt < 8; nt++)
#pragma unroll
            for (int j = 0; j < 4; j++) d[mt][nt][j] = 0.f;

    uint32_t aRel = (uint32_t)((wm * 32 + (lane & 7) + ((lane & 8) ? 8 : 0)) * ROWB
                               + ((lane & 16) ? 16 : 0));
    uint32_t bRel = (uint32_t)(OFF_B
                               + (wn * 64 + (lane & 7) + ((lane & 16) ? 8 : 0)) * ROWB
                               + ((lane & 8) ? 16 : 0));

    load_stage(sb, 0, 0, tid, brow, w0);
    CP_COMMIT();
    load_stage(sb, 1, 1, tid, brow, w0);
    CP_COMMIT();
    load_stage(sb, 2, 2, tid, brow, w0);
    CP_COMMIT();

    for (int it = 0; it < niter; it++) {
        CP_WAIT2();
        __syncthreads();
        int pf = it + 3;
        if (pf < niter) load_stage(sb, pf & (NSTAGE - 1), pf, tid, brow, w0);
        CP_COMMIT();

        uint32_t base = sb + (uint32_t)(it & (NSTAGE - 1)) * STAGE;
#pragma unroll
        for (int kc = 0; kc < 2; kc++) {
            uint32_t aH[2][4], bH[8][2];
#pragma unroll
            for (int mt = 0; mt < 2; mt++) {
                uint32_t ad = base + aRel + mt * (16 * ROWB) + kc * 32;
                LDSM4(aH[mt][0], aH[mt][1], aH[mt][2], aH[mt][3], ad);
            }
#pragma unroll
            for (int np = 0; np < 4; np++) {
                uint32_t bd = base + bRel + np * (16 * ROWB) + kc * 32;
                uint32_t r0, r1, r2, r3;
                LDSM4(r0, r1, r2, r3, bd);
                bH[2 * np][0] = r0; bH[2 * np][1] = r1;
                bH[2 * np + 1][0] = r2; bH[2 * np + 1][1] = r3;
            }
#pragma unroll
            for (int mt = 0; mt < 2; mt++)
#pragma unroll
                for (int nt = 0; nt < 8; nt++)
                    MMA16816(d[mt][nt], aH[mt], bH[nt]);
        }
    }

    int T = 126 - conv;
    int g = lane >> 2;
#pragma unroll
    for (int nt = 0; nt < 8; nt++) {
        float m0 = -FLT_MAX, m1 = -FLT_MAX;
#pragma unroll
        for (int mt = 0; mt < 2; mt++) {
            int r0 = wm * 32 + mt * 16 + g;
            if (r0 < T)     { m0 = fmaxf(m0, d[mt][nt][0]); m1 = fmaxf(m1, d[mt][nt][1]); }
            if (r0 + 8 < T) { m0 = fmaxf(m0, d[mt][nt][2]); m1 = fmaxf(m1, d[mt][nt][3]); }
        }
#pragma unroll
        for (int off = 4; off < 32; off <<= 1) {
            m0 = fmaxf(m0, __shfl_xor_sync(0xffffffffu, m0, off));
            m1 = fmaxf(m1, __shfl_xor_sync(0xffffffffu, m1, off));
        }
        if (g == 0) {
            int nc = wn * 64 + nt * 8 + (lane & 3) * 2;
            red[wm][nc] = m0;
            red[wm][nc + 1] = m1;
        }
    }
    __syncthreads();
    if (tid < 128) {
        float v = fmaxf(fmaxf(red[0][tid], red[1][tid]),
                        fmaxf(red[2][tid], red[3][tid]));
        g_sf[b * 768 + conv * 256 + f0 + tid] = v;
    }
}

// ---------------- head ----------------
__global__ void mlp_head(const float* __restrict__ cb3, const float* __restrict__ cb4,
                         const float* __restrict__ cb5,
                         const float* __restrict__ W1, const float* __restrict__ b1,
                         const float* __restrict__ W2, const float* __restrict__ b2,
                         float* __restrict__ out) {
    __shared__ float sf[768];
    __shared__ float gbuf[H2c];
    __shared__ float wsum[4][LABc];
    int b = blockIdx.x, tid = threadIdx.x;

    for (int i = tid; i < 768; i += 128) {
        int kf = i >> 8, f = i & 255;
        const float* cb = (kf == 0) ? cb3 : ((kf == 1) ? cb4 : cb5);
        sf[i] = tanhf(g_sf[b * 768 + i] + cb[f]);
    }
    __syncthreads();

    if (tid < H2c) {
        float s = b1[tid];
        const float* w = W1 + tid * 768;
        for (int c = 0; c < 768; c++) s += w[c] * sf[c];
        gbuf[tid] = tanhf(s);
    }
    __syncthreads();

    float part[LABc];
#pragma unroll
    for (int l = 0; l < LABc; l++) part[l] = 0.f;
    const float* fb = g_feat + b * 1900;
    for (int c = tid; c < 1900; c += 128) {
        float v = (c < 1800) ? fb[c] : gbuf[c - 1800];
#pragma unroll
        for (int l = 0; l < LABc; l++) part[l] += v * W2[l * 1900 + c];
    }
    int lane = tid & 31, wid = tid >> 5;
#pragma unroll
    for (int l = 0; l < LABc; l++) {
        float v = part[l];
        for (int s = 16; s; s >>= 1) v += __shfl_down_sync(0xffffffffu, v, s);
        if (lane == 0) wsum[wid][l] = v;
    }
    __syncthreads();
    if (tid < LABc)
        out[b * LABc + tid] = wsum[0][tid] + wsum[1][tid] + wsum[2][tid] + wsum[3][tid] + b2[tid];
}

// ---------------- launch ----------------
extern "C" void kernel_launch(void* const* d_in, const int* in_sizes, int n_in,
                              void* d_out, int out_size) {
    const int* inputs = (const int*)d_in[0];
    const int* e1s = (const int*)d_in[1];
    const int* e1e = (const int*)d_in[2];
    const int* e2s = (const int*)d_in[3];
    const int* e2e = (const int*)d_in[4];
    const int* p1 = (const int*)d_in[5];
    const int* p2 = (const int*)d_in[6];
    const float* emb = (const float*)d_in[7];
    const float* pos1 = (const float*)d_in[8];
    const float* pos2 = (const float*)d_in[9];
    const float* w3 = (const float*)d_in[10];
    const float* cb3 = (const float*)d_in[11];
    const float* w4 = (const float*)d_in[12];
    const float* cb4 = (const float*)d_in[13];
    const float* w5 = (const float*)d_in[14];
    const float* cb5 = (const float*)d_in[15];
    const float* W1 = (const float*)d_in[16];
    const float* b1 = (const float*)d_in[17];
    const float* W2 = (const float*)d_in[18];
    const float* b2 = (const float*)d_in[19];
    float* out = (float*)d_out;

    static int cfg_done = 0;
    if (!cfg_done) {
        cudaFuncSetAttribute(gemm_kernel, cudaFuncAttributeMaxDynamicSharedMemorySize,
                             GEMM_SMEM);
        cfg_done = 1;
    }

    prep_kernel<<<Bc * Lc + 768 + Bc, 256>>>(inputs, p1, p2, emb, pos1, pos2,
                                             w3, w4, w5, e1s, e1e, e2s, e2e);

    dim3 gg(Bc, 3, 2);
    gemm_kernel<<<gg, 256, GEMM_SMEM>>>();

    mlp_head<<<Bc, 128>>>(cb3, cb4, cb5, W1, b1, W2, b2, out);
}